// round 1
// baseline (speedup 1.0000x reference)
#include <cuda_runtime.h>
#include <math_constants.h>

#define NN      1024
#define HID     128
#define HEADS   4
#define HD      32
#define LAYERS  3

// ---------------- scratch (no allocs allowed) ----------------
__device__ float g_h[NN * HID];
__device__ float g_wlh[NN * HID];
__device__ float g_wrh[NN * HID];
__device__ float g_v[NN * HID];
__device__ float g_agg[NN * HID];
__device__ float g_pool[8 * HID];

// ---------------- input projection: h = relu(nf @ Wp + bp) ----------------
__global__ void proj_kernel(const float* __restrict__ nf,
                            const float* __restrict__ Wp,
                            const float* __restrict__ bp) {
    int i = blockIdx.x;
    int c = threadIdx.x;
    float a = bp[c]
            + nf[i * 3 + 0] * Wp[0 * HID + c]
            + nf[i * 3 + 1] * Wp[1 * HID + c]
            + nf[i * 3 + 2] * Wp[2 * HID + c];
    g_h[i * HID + c] = fmaxf(a, 0.f);
}

// ---------------- 3-way projection GEMM: wlh/wrh/v = h @ {Wl,Wr,Wv} ----------------
// grid (32, 3), block 128. Each block: 32 rows x 128 cols of one output.
__global__ void gemm3_kernel(const float* __restrict__ Wl,
                             const float* __restrict__ Wr,
                             const float* __restrict__ Wv) {
    const float* W;
    float* O;
    if (blockIdx.y == 0)      { W = Wl; O = g_wlh; }
    else if (blockIdx.y == 1) { W = Wr; O = g_wrh; }
    else                      { W = Wv; O = g_v; }

    int r0 = blockIdx.x * 32;
    int c  = threadIdx.x;

    __shared__ float hs[32 * HID];
    for (int t = threadIdx.x; t < 32 * HID; t += 128)
        hs[t] = g_h[r0 * HID + t];
    __syncthreads();

    float acc[32];
#pragma unroll
    for (int r = 0; r < 32; r++) acc[r] = 0.f;

    for (int k = 0; k < HID; k++) {
        float w = W[k * HID + c];
#pragma unroll
        for (int r = 0; r < 32; r++)
            acc[r] = fmaf(hs[r * HID + k], w, acc[r]);
    }
#pragma unroll
    for (int r = 0; r < 32; r++)
        O[(r0 + r) * HID + c] = acc[r];
}

// ---------------- fused GATv2 attention (flash-style online softmax) ----------------
// grid 1024 (one block per node i), block 128 (4 warps = 4 heads).
// lane owns accumulator dim d = lane.
__global__ void __launch_bounds__(128)
attn_kernel(const float* __restrict__ adj,
            const float* __restrict__ att) {
    int i    = blockIdx.x;
    int tid  = threadIdx.x;
    int h    = tid >> 5;
    int lane = tid & 31;

    __shared__ float wl_s[HID];
    __shared__ float att_s[HD];
    if (tid < HID) wl_s[tid] = g_wlh[i * HID + tid];
    if (tid < HD)  att_s[tid] = att[tid];
    __syncthreads();

    // register-cache this head's wlh row and the att vector
    float wlr[HD], ar[HD];
#pragma unroll
    for (int d = 0; d < HD; d++) { wlr[d] = wl_s[h * HD + d]; ar[d] = att_s[d]; }

    float run_m = -CUDART_INF_F;
    float s     = 0.f;
    float acc   = 0.f;   // dim d == lane

    const float* adj_row = adj + (size_t)i * NN;

    for (int j0 = 0; j0 < NN; j0 += 32) {
        int j = j0 + lane;

        // e[i,j,h] = sum_d lrelu(wlh[i,h,d] + wrh[j,h,d]) * att[d]
        const float4* wr4 = reinterpret_cast<const float4*>(g_wrh + j * HID + h * HD);
        float e = 0.f;
#pragma unroll
        for (int q = 0; q < 8; q++) {
            float4 w = wr4[q];
            float x;
            x = wlr[4*q+0] + w.x; x = fmaxf(x,0.f) + 0.2f*fminf(x,0.f); e = fmaf(x, ar[4*q+0], e);
            x = wlr[4*q+1] + w.y; x = fmaxf(x,0.f) + 0.2f*fminf(x,0.f); e = fmaf(x, ar[4*q+1], e);
            x = wlr[4*q+2] + w.z; x = fmaxf(x,0.f) + 0.2f*fminf(x,0.f); e = fmaf(x, ar[4*q+2], e);
            x = wlr[4*q+3] + w.w; x = fmaxf(x,0.f) + 0.2f*fminf(x,0.f); e = fmaf(x, ar[4*q+3], e);
        }
        float m_ij = (adj_row[j] > 0.5f) ? e : -1e9f;

        // warp max of this chunk
        float cm = m_ij;
#pragma unroll
        for (int o = 16; o; o >>= 1) cm = fmaxf(cm, __shfl_xor_sync(0xffffffffu, cm, o));

        float new_m = fmaxf(run_m, cm);
        float scale = __expf(run_m - new_m);   // exp(-inf)=0 on first chunk
        float p     = __expf(m_ij - new_m);

        float ps = p;
#pragma unroll
        for (int o = 16; o; o >>= 1) ps += __shfl_xor_sync(0xffffffffu, ps, o);

        s   = s * scale + ps;
        acc = acc * scale;
        run_m = new_m;

        // acc[d=lane] += sum_jj p[jj] * v[j0+jj, h, lane]
        const float* vb = g_v + (size_t)j0 * HID + h * HD + lane;
#pragma unroll
        for (int jj = 0; jj < 32; jj++) {
            float pj = __shfl_sync(0xffffffffu, p, jj);
            acc = fmaf(pj, vb[(size_t)jj * HID], acc);
        }
    }

    g_agg[i * HID + h * HD + lane] = acc / s;
}

// ---------------- layernorm + relu + residual: h += relu(LN(agg)*gamma+beta) ----------------
__global__ void ln_kernel(const float* __restrict__ gamma,
                          const float* __restrict__ beta) {
    int i = blockIdx.x;
    int t = threadIdx.x;
    float x = g_agg[i * HID + t];

    float s1 = x, s2 = x * x;
#pragma unroll
    for (int o = 16; o; o >>= 1) {
        s1 += __shfl_xor_sync(0xffffffffu, s1, o);
        s2 += __shfl_xor_sync(0xffffffffu, s2, o);
    }
    __shared__ float a1[4], a2[4];
    int w = t >> 5;
    if ((t & 31) == 0) { a1[w] = s1; a2[w] = s2; }
    __syncthreads();
    float S1 = a1[0] + a1[1] + a1[2] + a1[3];
    float S2 = a2[0] + a2[1] + a2[2] + a2[3];
    float mu  = S1 * (1.f / HID);
    float var = S2 * (1.f / HID) - mu * mu;
    float y = (x - mu) * rsqrtf(var + 1e-5f) * gamma[t] + beta[t];
    g_h[i * HID + t] += fmaxf(y, 0.f);
}

// ---------------- node_logits + delta_mu heads ----------------
// grid 1024, block 64
__global__ void heads_kernel(const float* __restrict__ Wn1, const float* __restrict__ bn1,
                             const float* __restrict__ Wn2, const float* __restrict__ bn2,
                             const float* __restrict__ Wd1, const float* __restrict__ bd1,
                             const float* __restrict__ Wd2, const float* __restrict__ bd2,
                             float* __restrict__ out) {
    int i = blockIdx.x;
    int c = threadIdx.x; // 0..63

    __shared__ float hs[HID];
    hs[c]      = g_h[i * HID + c];
    hs[c + 64] = g_h[i * HID + 64 + c];
    __syncthreads();

    float an = bn1[c], ad = bd1[c];
    for (int k = 0; k < HID; k++) {
        float hk = hs[k];
        an = fmaf(hk, Wn1[k * 64 + c], an);
        ad = fmaf(hk, Wd1[k * 64 + c], ad);
    }
    an = fmaxf(an, 0.f);
    ad = fmaxf(ad, 0.f);

    float pn = an * Wn2[c];
    float p0 = ad * Wd2[c * 2 + 0];
    float p1 = ad * Wd2[c * 2 + 1];
#pragma unroll
    for (int o = 16; o; o >>= 1) {
        pn += __shfl_xor_sync(0xffffffffu, pn, o);
        p0 += __shfl_xor_sync(0xffffffffu, p0, o);
        p1 += __shfl_xor_sync(0xffffffffu, p1, o);
    }
    __shared__ float rn[2], r0s[2], r1s[2];
    if ((c & 31) == 0) { rn[c >> 5] = pn; r0s[c >> 5] = p0; r1s[c >> 5] = p1; }
    __syncthreads();
    if (c == 0) {
        out[i]                 = rn[0] + rn[1] + bn2[0];
        out[NN + 2 * i + 0]    = r0s[0] + r0s[1] + bd2[0];
        out[NN + 2 * i + 1]    = r1s[0] + r1s[1] + bd2[1];
    }
}

// ---------------- pooled value head ----------------
__global__ void pool_kernel() { // grid 8, block 128
    int b = blockIdx.x, c = threadIdx.x;
    float s = 0.f;
    for (int r = 0; r < 128; r++)
        s += g_h[(size_t)(b * 128 + r) * HID + c];
    g_pool[b * HID + c] = s;
}

__global__ void value_kernel(const float* __restrict__ Wv1, const float* __restrict__ bv1,
                             const float* __restrict__ Wv2, const float* __restrict__ bv2,
                             float* __restrict__ out) { // 1 block, 128 threads
    int t = threadIdx.x;
    __shared__ float ps[HID];
    float s = 0.f;
#pragma unroll
    for (int b = 0; b < 8; b++) s += g_pool[b * HID + t];
    ps[t] = s * (1.f / NN);
    __syncthreads();

    float p = 0.f;
    if (t < 64) {
        float a = bv1[t];
        for (int k = 0; k < HID; k++) a = fmaf(ps[k], Wv1[k * 64 + t], a);
        a = fmaxf(a, 0.f);
        p = a * Wv2[t];
    }
#pragma unroll
    for (int o = 16; o; o >>= 1) p += __shfl_xor_sync(0xffffffffu, p, o);
    __shared__ float red[4];
    if ((t & 31) == 0) red[t >> 5] = p;
    __syncthreads();
    if (t == 0) out[NN + 2 * NN] = red[0] + red[1] + red[2] + red[3] + bv2[0];
}

// ---------------- launch ----------------
extern "C" void kernel_launch(void* const* d_in, const int* in_sizes, int n_in,
                              void* d_out, int out_size) {
    const float* nf    = (const float*)d_in[0];
    const float* adj   = (const float*)d_in[1];
    const float* Wp    = (const float*)d_in[2];
    const float* bp    = (const float*)d_in[3];
    const float* Wl    = (const float*)d_in[4];
    const float* Wr    = (const float*)d_in[5];
    const float* Wv    = (const float*)d_in[6];
    const float* att   = (const float*)d_in[7];
    const float* gamma = (const float*)d_in[8];
    const float* beta  = (const float*)d_in[9];
    const float* Wn1   = (const float*)d_in[10];
    const float* bn1   = (const float*)d_in[11];
    const float* Wn2   = (const float*)d_in[12];
    const float* bn2   = (const float*)d_in[13];
    const float* Wd1   = (const float*)d_in[14];
    const float* bd1   = (const float*)d_in[15];
    const float* Wd2   = (const float*)d_in[16];
    const float* bd2   = (const float*)d_in[17];
    const float* Wv1   = (const float*)d_in[18];
    const float* bv1   = (const float*)d_in[19];
    const float* Wv2   = (const float*)d_in[20];
    const float* bv2   = (const float*)d_in[21];
    float* out = (float*)d_out;

    proj_kernel<<<NN, HID>>>(nf, Wp, bp);

    for (int l = 0; l < LAYERS; l++) {
        gemm3_kernel<<<dim3(32, 3), 128>>>(Wl + l * HID * HID,
                                           Wr + l * HID * HID,
                                           Wv + l * HID * HID);
        attn_kernel<<<NN, 128>>>(adj, att + l * HD);
        ln_kernel<<<NN, HID>>>(gamma + l * HID, beta + l * HID);
    }

    heads_kernel<<<NN, 64>>>(Wn1, bn1, Wn2, bn2, Wd1, bd1, Wd2, bd2, out);
    pool_kernel<<<8, 128>>>();
    value_kernel<<<1, 128>>>(Wv1, bv1, Wv2, bv2, out);
}

// round 2
// speedup vs baseline: 1.9121x; 1.9121x over previous
#include <cuda_runtime.h>
#include <math_constants.h>

#define NN      1024
#define HID     128
#define HEADS   4
#define HD      32
#define LAYERS  3
#define TI      8          // i-rows per block in attention
#define NSEG    4          // j-segments (one per warp-group of 4 head-warps)
#define SEGJ    (NN/NSEG)  // 256
#define ADJW    (NN/32)    // 32 words per adjacency row

// ---------------- scratch (no allocs allowed) ----------------
__device__ __align__(128) float    g_h[NN * HID];
__device__ __align__(128) float    g_wlh[NN * HID];
__device__ __align__(128) float    g_wrhT[HID * NN];   // [h*HD+d][j]
__device__ __align__(128) float    g_v[NN * HID];
__device__ __align__(128) unsigned g_adjbits[NN * ADJW];
__device__ __align__(128) float    g_pool[8 * HID];

// ---------------- adjacency -> bitmask ----------------
__global__ void adjbits_kernel(const float* __restrict__ adj) {
    int i    = blockIdx.x * 8 + (threadIdx.x >> 5);
    int lane = threadIdx.x & 31;
    for (int w = 0; w < ADJW; w++) {
        float v = adj[(size_t)i * NN + w * 32 + lane];
        unsigned b = __ballot_sync(0xffffffffu, v > 0.5f);
        if (lane == 0) g_adjbits[i * ADJW + w] = b;
    }
}

// ---------------- input projection: h = relu(nf @ Wp + bp) ----------------
__global__ void proj_kernel(const float* __restrict__ nf,
                            const float* __restrict__ Wp,
                            const float* __restrict__ bp) {
    int i = blockIdx.x;
    int c = threadIdx.x;
    float a = bp[c]
            + nf[i * 3 + 0] * Wp[0 * HID + c]
            + nf[i * 3 + 1] * Wp[1 * HID + c]
            + nf[i * 3 + 2] * Wp[2 * HID + c];
    g_h[i * HID + c] = fmaxf(a, 0.f);
}

// ---------------- 3-way projection GEMM ----------------
// grid (32, 3), block 128. y=0 -> wlh, y=1 -> wrhT (transposed), y=2 -> v.
__global__ void __launch_bounds__(128)
gemm3_kernel(const float* __restrict__ Wl,
             const float* __restrict__ Wr,
             const float* __restrict__ Wv) {
    __shared__ float hs[32 * 133];   // padded stride 133 (conflict-free transpose)
    const float* W;
    float* O = nullptr;
    int mode = blockIdx.y;
    if (mode == 0)      { W = Wl; O = g_wlh; }
    else if (mode == 1) { W = Wr; }
    else                { W = Wv; O = g_v; }

    int r0 = blockIdx.x * 32;
    int c  = threadIdx.x;

    for (int t = c; t < 32 * HID; t += 128)
        hs[(t >> 7) * 133 + (t & 127)] = g_h[r0 * HID + t];
    __syncthreads();

    float acc[32];
#pragma unroll
    for (int r = 0; r < 32; r++) acc[r] = 0.f;

    for (int k = 0; k < HID; k++) {
        float w = W[k * HID + c];
#pragma unroll
        for (int r = 0; r < 32; r++)
            acc[r] = fmaf(hs[r * 133 + k], w, acc[r]);
    }

    if (mode != 1) {
#pragma unroll
        for (int r = 0; r < 32; r++)
            O[(r0 + r) * HID + c] = acc[r];
    } else {
        __syncthreads();
#pragma unroll
        for (int r = 0; r < 32; r++)
            hs[r * 133 + c] = acc[r];
        __syncthreads();
        int lane = c & 31, wp = c >> 5;
        for (int cc = wp; cc < HID; cc += 4)
            g_wrhT[cc * NN + r0 + lane] = hs[lane * 133 + cc];
    }
}

// ---------------- fused GATv2 attention + merge + LN + residual ----------------
// grid NN/TI = 128 blocks, 512 threads = 16 warps: warp = (head h = w&3, seg = w>>2).
// Each warp: 8 i-rows, head h, j-range [seg*256, seg*256+256), flash online softmax.
__global__ void __launch_bounds__(512, 1)
attn_kernel(const float* __restrict__ att,
            const float* __restrict__ gamma,
            const float* __restrict__ beta) {
    const int i0   = blockIdx.x * TI;
    const int tid  = threadIdx.x;
    const int warp = tid >> 5;
    const int lane = tid & 31;
    const int h    = warp & 3;
    const int seg  = warp >> 2;

    __shared__ __align__(16) float wl_s[TI][HID];
    __shared__ __align__(16) float att_s[HD];
    __shared__ float a6_s[HEADS][TI];
    __shared__ float m_s[HEADS][NSEG][TI];
    __shared__ float s_s[HEADS][NSEG][TI];
    __shared__ float acc_s[HEADS][NSEG][TI][HD];
    __shared__ __align__(16) float agg_s[TI][HID];

    for (int t = tid; t < TI * HID; t += 512)
        wl_s[t >> 7][t & 127] = g_wlh[i0 * HID + t];
    if (tid < HD) att_s[tid] = att[tid];
    __syncthreads();

    // a6[h][i] = 0.6 * sum_d wl[i][h,d]*att[d]
    for (int t = warp; t < HEADS * TI; t += 16) {
        int ii = t >> 2, hh = t & 3;
        float v = wl_s[ii][hh * HD + lane] * att_s[lane];
#pragma unroll
        for (int o = 16; o; o >>= 1) v += __shfl_xor_sync(0xffffffffu, v, o);
        if (lane == 0) a6_s[hh][ii] = 0.6f * v;
    }
    __syncthreads();

    float m[TI], s[TI], acc[TI];
#pragma unroll
    for (int ii = 0; ii < TI; ii++) { m[ii] = -CUDART_INF_F; s[ii] = 0.f; acc[ii] = 0.f; }

    const int jbase = seg * SEGJ;
#pragma unroll 1
    for (int c = 0; c < SEGJ / 32; c++) {
        const int j0 = jbase + c * 32;
        const int j  = j0 + lane;

        // coalesced loads: wr[d] from transposed layout, v[jj] for lane = d
        float wr[HD];
#pragma unroll
        for (int d = 0; d < HD; d++)
            wr[d] = g_wrhT[(h * HD + d) * NN + j];
        float vv[32];
#pragma unroll
        for (int jj = 0; jj < 32; jj++)
            vv[jj] = g_v[(j0 + jj) * HID + h * HD + lane];

        // e = 0.6*(a_i + b_j) + 0.4 * sum_d |wl+wr|*att
        float csum[TI];
#pragma unroll
        for (int ii = 0; ii < TI; ii++) csum[ii] = 0.f;
        float b = 0.f;
#pragma unroll
        for (int q = 0; q < HD / 4; q++) {
            float4 at = *(const float4*)&att_s[4 * q];
            float w0 = wr[4*q+0], w1 = wr[4*q+1], w2 = wr[4*q+2], w3 = wr[4*q+3];
            b = fmaf(w0, at.x, b); b = fmaf(w1, at.y, b);
            b = fmaf(w2, at.z, b); b = fmaf(w3, at.w, b);
#pragma unroll
            for (int ii = 0; ii < TI; ii++) {
                float4 wl4 = *(const float4*)&wl_s[ii][h * HD + 4 * q];
                csum[ii] = fmaf(fabsf(wl4.x + w0), at.x, csum[ii]);
                csum[ii] = fmaf(fabsf(wl4.y + w1), at.y, csum[ii]);
                csum[ii] = fmaf(fabsf(wl4.z + w2), at.z, csum[ii]);
                csum[ii] = fmaf(fabsf(wl4.w + w3), at.w, csum[ii]);
            }
        }
        float b6 = 0.6f * b;

#pragma unroll
        for (int ii = 0; ii < TI; ii++) {
            unsigned aw = g_adjbits[(i0 + ii) * ADJW + (j0 >> 5)];
            float e = ((aw >> lane) & 1u) ? fmaf(0.4f, csum[ii], a6_s[h][ii] + b6)
                                          : -1e9f;
            float cm = e;
#pragma unroll
            for (int o = 16; o; o >>= 1) cm = fmaxf(cm, __shfl_xor_sync(0xffffffffu, cm, o));
            float nm = fmaxf(m[ii], cm);
            float sc = __expf(m[ii] - nm);   // exp(-inf)=0 on first chunk
            float p  = __expf(e - nm);
            float ps = p;
#pragma unroll
            for (int o = 16; o; o >>= 1) ps += __shfl_xor_sync(0xffffffffu, ps, o);
            s[ii] = fmaf(s[ii], sc, ps);
            m[ii] = nm;
            float av = acc[ii] * sc;
#pragma unroll
            for (int jj = 0; jj < 32; jj++)
                av = fmaf(__shfl_sync(0xffffffffu, p, jj), vv[jj], av);
            acc[ii] = av;
        }
    }

    // publish per-segment flash state
#pragma unroll
    for (int ii = 0; ii < TI; ii++) {
        if (lane == 0) { m_s[h][seg][ii] = m[ii]; s_s[h][seg][ii] = s[ii]; }
        acc_s[h][seg][ii][lane] = acc[ii];
    }
    __syncthreads();

    // merge 4 segments per (i, head)
    for (int t = warp; t < HEADS * TI; t += 16) {
        int ii = t >> 2, hh = t & 3;
        float m0 = m_s[hh][0][ii], m1 = m_s[hh][1][ii];
        float m2 = m_s[hh][2][ii], m3 = m_s[hh][3][ii];
        float M = fmaxf(fmaxf(m0, m1), fmaxf(m2, m3));
        float w0 = __expf(m0 - M), w1 = __expf(m1 - M);
        float w2 = __expf(m2 - M), w3 = __expf(m3 - M);
        float S = s_s[hh][0][ii] * w0 + s_s[hh][1][ii] * w1
                + s_s[hh][2][ii] * w2 + s_s[hh][3][ii] * w3;
        float A =      acc_s[hh][0][ii][lane] * w0;
        A = fmaf(acc_s[hh][1][ii][lane], w1, A);
        A = fmaf(acc_s[hh][2][ii][lane], w2, A);
        A = fmaf(acc_s[hh][3][ii][lane], w3, A);
        agg_s[ii][hh * HD + lane] = A / S;
    }
    __syncthreads();

    // LN + relu + residual (warp = row)
    if (warp < TI) {
        const int ii = warp;
        float4 x = *(const float4*)&agg_s[ii][lane * 4];
        float s1 = x.x + x.y + x.z + x.w;
        float s2 = x.x*x.x + x.y*x.y + x.z*x.z + x.w*x.w;
#pragma unroll
        for (int o = 16; o; o >>= 1) {
            s1 += __shfl_xor_sync(0xffffffffu, s1, o);
            s2 += __shfl_xor_sync(0xffffffffu, s2, o);
        }
        float mu  = s1 * (1.f / HID);
        float var = s2 * (1.f / HID) - mu * mu;
        float rs  = rsqrtf(var + 1e-5f);
        float4 gm = *(const float4*)&gamma[lane * 4];
        float4 bt = *(const float4*)&beta[lane * 4];
        float4 hv = *(float4*)&g_h[(i0 + ii) * HID + lane * 4];
        hv.x += fmaxf((x.x - mu) * rs * gm.x + bt.x, 0.f);
        hv.y += fmaxf((x.y - mu) * rs * gm.y + bt.y, 0.f);
        hv.z += fmaxf((x.z - mu) * rs * gm.z + bt.z, 0.f);
        hv.w += fmaxf((x.w - mu) * rs * gm.w + bt.w, 0.f);
        *(float4*)&g_h[(i0 + ii) * HID + lane * 4] = hv;
    }
}

// ---------------- node_logits + delta_mu heads (16 i per block) ----------------
__global__ void __launch_bounds__(128)
heads_kernel(const float* __restrict__ Wn1, const float* __restrict__ bn1,
             const float* __restrict__ Wn2, const float* __restrict__ bn2,
             const float* __restrict__ Wd1, const float* __restrict__ bd1,
             const float* __restrict__ Wd2, const float* __restrict__ bd2,
             float* __restrict__ out) {
    __shared__ float hs[16][HID];
    __shared__ float redA[4][16], redB[4][16];
    int i0 = blockIdx.x * 16;
    int tid = threadIdx.x;
    int c = tid & 63, g = tid >> 6;

    for (int t = tid; t < 16 * HID; t += 128)
        hs[t >> 7][t & 127] = g_h[i0 * HID + t];
    __syncthreads();

    const float* W1 = g ? Wd1 : Wn1;
    float bb = g ? bd1[c] : bn1[c];
    float acc[16];
#pragma unroll
    for (int r = 0; r < 16; r++) acc[r] = bb;
    for (int k = 0; k < HID; k++) {
        float w = W1[k * 64 + c];
#pragma unroll
        for (int r = 0; r < 16; r++)
            acc[r] = fmaf(hs[r][k], w, acc[r]);
    }

    float w2a = g ? Wd2[c * 2 + 0] : Wn2[c];
    float w2b = g ? Wd2[c * 2 + 1] : 0.f;
    int warp = tid >> 5, lane = tid & 31;
#pragma unroll
    for (int r = 0; r < 16; r++) {
        float ar = fmaxf(acc[r], 0.f);
        float ya = ar * w2a, yb = ar * w2b;
#pragma unroll
        for (int o = 16; o; o >>= 1) {
            ya += __shfl_xor_sync(0xffffffffu, ya, o);
            yb += __shfl_xor_sync(0xffffffffu, yb, o);
        }
        if (lane == 0) { redA[warp][r] = ya; redB[warp][r] = yb; }
    }
    __syncthreads();

    if (tid < 16) {
        out[i0 + tid] = redA[0][tid] + redA[1][tid] + bn2[0];
    } else if (tid < 32) {
        int r = tid - 16;
        out[NN + 2 * (i0 + r) + 0] = redA[2][r] + redA[3][r] + bd2[0];
        out[NN + 2 * (i0 + r) + 1] = redB[2][r] + redB[3][r] + bd2[1];
    }
}

// ---------------- pooled value head ----------------
__global__ void pool_kernel() { // grid 8, block 128
    int b = blockIdx.x, c = threadIdx.x;
    float s = 0.f;
    for (int r = 0; r < 128; r++)
        s += g_h[(size_t)(b * 128 + r) * HID + c];
    g_pool[b * HID + c] = s;
}

__global__ void value_kernel(const float* __restrict__ Wv1, const float* __restrict__ bv1,
                             const float* __restrict__ Wv2, const float* __restrict__ bv2,
                             float* __restrict__ out) { // 1 block, 128 threads
    int t = threadIdx.x;
    __shared__ float ps[HID];
    float s = 0.f;
#pragma unroll
    for (int b = 0; b < 8; b++) s += g_pool[b * HID + t];
    ps[t] = s * (1.f / NN);
    __syncthreads();

    float p = 0.f;
    if (t < 64) {
        float a = bv1[t];
        for (int k = 0; k < HID; k++) a = fmaf(ps[k], Wv1[k * 64 + t], a);
        a = fmaxf(a, 0.f);
        p = a * Wv2[t];
    }
#pragma unroll
    for (int o = 16; o; o >>= 1) p += __shfl_xor_sync(0xffffffffu, p, o);
    __shared__ float red[4];
    if ((t & 31) == 0) red[t >> 5] = p;
    __syncthreads();
    if (t == 0) out[NN + 2 * NN] = red[0] + red[1] + red[2] + red[3] + bv2[0];
}

// ---------------- launch ----------------
extern "C" void kernel_launch(void* const* d_in, const int* in_sizes, int n_in,
                              void* d_out, int out_size) {
    const float* nf    = (const float*)d_in[0];
    const float* adj   = (const float*)d_in[1];
    const float* Wp    = (const float*)d_in[2];
    const float* bp    = (const float*)d_in[3];
    const float* Wl    = (const float*)d_in[4];
    const float* Wr    = (const float*)d_in[5];
    const float* Wv    = (const float*)d_in[6];
    const float* att   = (const float*)d_in[7];
    const float* gamma = (const float*)d_in[8];
    const float* beta  = (const float*)d_in[9];
    const float* Wn1   = (const float*)d_in[10];
    const float* bn1   = (const float*)d_in[11];
    const float* Wn2   = (const float*)d_in[12];
    const float* bn2   = (const float*)d_in[13];
    const float* Wd1   = (const float*)d_in[14];
    const float* bd1   = (const float*)d_in[15];
    const float* Wd2   = (const float*)d_in[16];
    const float* bd2   = (const float*)d_in[17];
    const float* Wv1   = (const float*)d_in[18];
    const float* bv1   = (const float*)d_in[19];
    const float* Wv2   = (const float*)d_in[20];
    const float* bv2   = (const float*)d_in[21];
    float* out = (float*)d_out;

    adjbits_kernel<<<128, 256>>>(adj);
    proj_kernel<<<NN, HID>>>(nf, Wp, bp);

    for (int l = 0; l < LAYERS; l++) {
        gemm3_kernel<<<dim3(32, 3), 128>>>(Wl + l * HID * HID,
                                           Wr + l * HID * HID,
                                           Wv + l * HID * HID);
        attn_kernel<<<NN / TI, 512>>>(att + l * HD, gamma + l * HID, beta + l * HID);
    }

    heads_kernel<<<64, 128>>>(Wn1, bn1, Wn2, bn2, Wd1, bd1, Wd2, bd2, out);
    pool_kernel<<<8, 128>>>();
    value_kernel<<<1, 128>>>(Wv1, bv1, Wv2, bv2, out);
}

// round 3
// speedup vs baseline: 3.1431x; 1.6438x over previous
#include <cuda_runtime.h>
#include <math_constants.h>

#define NN      1024
#define HID     128
#define HEADS   4
#define HD      32
#define LAYERS  3
#define TI      4          // i-rows per block in attention
#define NSEG    2          // j-segments
#define SEGJ    (NN/NSEG)  // 512
#define ADJW    (NN/32)    // 32 words per adjacency row

// ---------------- scratch (no allocs allowed) ----------------
__device__ __align__(128) float    g_h[NN * HID];
__device__ __align__(128) float    g_wlh[NN * HID];
__device__ __align__(128) float    g_wrhT[HID * NN];   // [h*HD+d][j]
__device__ __align__(128) float    g_v[NN * HID];
__device__ __align__(128) unsigned g_adjbits[NN * ADJW];
__device__ __align__(128) float    g_pool[8 * HID];

// ---------------- adjacency -> bitmask ----------------
__global__ void adjbits_kernel(const float* __restrict__ adj) {
    int i    = blockIdx.x * 8 + (threadIdx.x >> 5);
    int lane = threadIdx.x & 31;
    for (int w = 0; w < ADJW; w++) {
        float v = adj[(size_t)i * NN + w * 32 + lane];
        unsigned b = __ballot_sync(0xffffffffu, v > 0.5f);
        if (lane == 0) g_adjbits[i * ADJW + w] = b;
    }
}

// ---------------- input projection: h = relu(nf @ Wp + bp) ----------------
__global__ void proj_kernel(const float* __restrict__ nf,
                            const float* __restrict__ Wp,
                            const float* __restrict__ bp) {
    int i = blockIdx.x;
    int c = threadIdx.x;
    float a = bp[c]
            + nf[i * 3 + 0] * Wp[0 * HID + c]
            + nf[i * 3 + 1] * Wp[1 * HID + c]
            + nf[i * 3 + 2] * Wp[2 * HID + c];
    g_h[i * HID + c] = fmaxf(a, 0.f);
}

// ---------------- 3-way projection GEMM ----------------
// grid (32, 3), block 128. y=0 -> wlh, y=1 -> wrhT (transposed), y=2 -> v.
__global__ void __launch_bounds__(128)
gemm3_kernel(const float* __restrict__ Wl,
             const float* __restrict__ Wr,
             const float* __restrict__ Wv) {
    __shared__ float hs[32 * 133];   // padded stride 133 (conflict-free transpose)
    const float* W;
    float* O = nullptr;
    int mode = blockIdx.y;
    if (mode == 0)      { W = Wl; O = g_wlh; }
    else if (mode == 1) { W = Wr; }
    else                { W = Wv; O = g_v; }

    int r0 = blockIdx.x * 32;
    int c  = threadIdx.x;

    for (int t = c; t < 32 * HID; t += 128)
        hs[(t >> 7) * 133 + (t & 127)] = g_h[r0 * HID + t];
    __syncthreads();

    float acc[32];
#pragma unroll
    for (int r = 0; r < 32; r++) acc[r] = 0.f;

    for (int k = 0; k < HID; k++) {
        float w = W[k * HID + c];
#pragma unroll
        for (int r = 0; r < 32; r++)
            acc[r] = fmaf(hs[r * 133 + k], w, acc[r]);
    }

    if (mode != 1) {
#pragma unroll
        for (int r = 0; r < 32; r++)
            O[(r0 + r) * HID + c] = acc[r];
    } else {
        __syncthreads();
#pragma unroll
        for (int r = 0; r < 32; r++)
            hs[r * 133 + c] = acc[r];
        __syncthreads();
        int lane = c & 31, wp = c >> 5;
        for (int cc = wp; cc < HID; cc += 4)
            g_wrhT[cc * NN + r0 + lane] = hs[lane * 133 + cc];
    }
}

// ---------------- fused GATv2 attention + merge + LN + residual ----------------
// grid NN/TI = 256 blocks, 256 threads = 8 warps: warp = (head h = w&3, seg = w>>2).
// No online max (softmax shift-invariance: the i-constant term is dropped exactly;
// remaining exponent is O(+-10), safe in fp32). s accumulated per-lane.
__global__ void __launch_bounds__(256, 3)
attn_kernel(const float* __restrict__ att,
            const float* __restrict__ gamma,
            const float* __restrict__ beta) {
    const int i0   = blockIdx.x * TI;
    const int tid  = threadIdx.x;
    const int warp = tid >> 5;
    const int lane = tid & 31;
    const int h    = warp & 3;
    const int seg  = warp >> 2;

    __shared__ __align__(16) float wl_s[TI][HID];
    __shared__ __align__(16) float att_s[HD];
    __shared__ __align__(16) float p_s[8][32][4];     // [warp][jj][ii]
    __shared__ float s_s[HEADS][NSEG][TI];
    __shared__ float acc_s[HEADS][NSEG][TI][HD];
    __shared__ __align__(16) float agg_s[TI][HID];

    for (int t = tid; t < TI * HID; t += 256)
        wl_s[t >> 7][t & 127] = g_wlh[i0 * HID + t];
    if (tid < HD) att_s[tid] = att[tid];
    __syncthreads();

    float s0 = 0.f, s1 = 0.f, s2 = 0.f, s3 = 0.f;
    float a0 = 0.f, a1 = 0.f, a2 = 0.f, a3 = 0.f;   // acc, lane = d

    const int jbase = seg * SEGJ;
#pragma unroll 1
    for (int c = 0; c < SEGJ / 32; c++) {
        const int j0 = jbase + c * 32;
        const int j  = j0 + lane;

        float b = 0.f, c0 = 0.f, c1 = 0.f, c2 = 0.f, c3 = 0.f;

        // ---- scores: two half-passes over d to cap live registers ----
#pragma unroll
        for (int half = 0; half < 2; half++) {
            float wr[16];
#pragma unroll
            for (int d = 0; d < 16; d++)
                wr[d] = g_wrhT[(h * HD + half * 16 + d) * NN + j];
#pragma unroll
            for (int q = 0; q < 4; q++) {
                float4 at = *(const float4*)&att_s[half * 16 + 4 * q];
                float w0 = wr[4*q+0], w1 = wr[4*q+1], w2 = wr[4*q+2], w3 = wr[4*q+3];
                b = fmaf(w0, at.x, b); b = fmaf(w1, at.y, b);
                b = fmaf(w2, at.z, b); b = fmaf(w3, at.w, b);
                const int off = h * HD + half * 16 + 4 * q;
                float4 l;
                l = *(const float4*)&wl_s[0][off];
                c0 = fmaf(fabsf(l.x + w0), at.x, c0); c0 = fmaf(fabsf(l.y + w1), at.y, c0);
                c0 = fmaf(fabsf(l.z + w2), at.z, c0); c0 = fmaf(fabsf(l.w + w3), at.w, c0);
                l = *(const float4*)&wl_s[1][off];
                c1 = fmaf(fabsf(l.x + w0), at.x, c1); c1 = fmaf(fabsf(l.y + w1), at.y, c1);
                c1 = fmaf(fabsf(l.z + w2), at.z, c1); c1 = fmaf(fabsf(l.w + w3), at.w, c1);
                l = *(const float4*)&wl_s[2][off];
                c2 = fmaf(fabsf(l.x + w0), at.x, c2); c2 = fmaf(fabsf(l.y + w1), at.y, c2);
                c2 = fmaf(fabsf(l.z + w2), at.z, c2); c2 = fmaf(fabsf(l.w + w3), at.w, c2);
                l = *(const float4*)&wl_s[3][off];
                c3 = fmaf(fabsf(l.x + w0), at.x, c3); c3 = fmaf(fabsf(l.y + w1), at.y, c3);
                c3 = fmaf(fabsf(l.z + w2), at.z, c3); c3 = fmaf(fabsf(l.w + w3), at.w, c3);
            }
        }
        float b6 = 0.6f * b;

        const int widx = j0 >> 5;
        unsigned aw0 = g_adjbits[(i0 + 0) * ADJW + widx];
        unsigned aw1 = g_adjbits[(i0 + 1) * ADJW + widx];
        unsigned aw2 = g_adjbits[(i0 + 2) * ADJW + widx];
        unsigned aw3 = g_adjbits[(i0 + 3) * ADJW + widx];
        float p0 = ((aw0 >> lane) & 1u) ? __expf(fmaf(0.4f, c0, b6)) : 0.f;
        float p1 = ((aw1 >> lane) & 1u) ? __expf(fmaf(0.4f, c1, b6)) : 0.f;
        float p2 = ((aw2 >> lane) & 1u) ? __expf(fmaf(0.4f, c2, b6)) : 0.f;
        float p3 = ((aw3 >> lane) & 1u) ? __expf(fmaf(0.4f, c3, b6)) : 0.f;
        s0 += p0; s1 += p1; s2 += p2; s3 += p3;

        *(float4*)&p_s[warp][lane][0] = make_float4(p0, p1, p2, p3);
        __syncwarp();

        // ---- acc[d=lane] += p[jj] * v[j0+jj, h, lane], two half-passes ----
        const float* vb = g_v + (size_t)j0 * HID + h * HD + lane;
#pragma unroll
        for (int half = 0; half < 2; half++) {
            float vv[16];
#pragma unroll
            for (int jj = 0; jj < 16; jj++)
                vv[jj] = vb[(size_t)(half * 16 + jj) * HID];
#pragma unroll
            for (int jj = 0; jj < 16; jj++) {
                float4 pj = *(const float4*)&p_s[warp][half * 16 + jj][0];
                a0 = fmaf(pj.x, vv[jj], a0);
                a1 = fmaf(pj.y, vv[jj], a1);
                a2 = fmaf(pj.z, vv[jj], a2);
                a3 = fmaf(pj.w, vv[jj], a3);
            }
        }
        __syncwarp();
    }

    // ---- publish per-segment sums ----
    float sv[4] = {s0, s1, s2, s3};
    float av[4] = {a0, a1, a2, a3};
#pragma unroll
    for (int ii = 0; ii < TI; ii++) {
        float t = sv[ii];
#pragma unroll
        for (int o = 16; o; o >>= 1) t += __shfl_xor_sync(0xffffffffu, t, o);
        if (lane == 0) s_s[h][seg][ii] = t;
        acc_s[h][seg][ii][lane] = av[ii];
    }
    __syncthreads();

    // ---- merge 2 segments (plain sums, no max bookkeeping) ----
    for (int t = warp; t < HEADS * TI; t += 8) {
        int ii = t >> 2, hh = t & 3;
        float S = s_s[hh][0][ii] + s_s[hh][1][ii];
        float A = acc_s[hh][0][ii][lane] + acc_s[hh][1][ii][lane];
        agg_s[ii][hh * HD + lane] = A / S;
    }
    __syncthreads();

    // ---- LN + relu + residual (warp = row) ----
    if (warp < TI) {
        const int ii = warp;
        float4 x = *(const float4*)&agg_s[ii][lane * 4];
        float m1 = x.x + x.y + x.z + x.w;
        float m2 = x.x*x.x + x.y*x.y + x.z*x.z + x.w*x.w;
#pragma unroll
        for (int o = 16; o; o >>= 1) {
            m1 += __shfl_xor_sync(0xffffffffu, m1, o);
            m2 += __shfl_xor_sync(0xffffffffu, m2, o);
        }
        float mu  = m1 * (1.f / HID);
        float var = m2 * (1.f / HID) - mu * mu;
        float rs  = rsqrtf(var + 1e-5f);
        float4 gm = *(const float4*)&gamma[lane * 4];
        float4 bt = *(const float4*)&beta[lane * 4];
        float4 hv = *(float4*)&g_h[(i0 + ii) * HID + lane * 4];
        hv.x += fmaxf((x.x - mu) * rs * gm.x + bt.x, 0.f);
        hv.y += fmaxf((x.y - mu) * rs * gm.y + bt.y, 0.f);
        hv.z += fmaxf((x.z - mu) * rs * gm.z + bt.z, 0.f);
        hv.w += fmaxf((x.w - mu) * rs * gm.w + bt.w, 0.f);
        *(float4*)&g_h[(i0 + ii) * HID + lane * 4] = hv;
    }
}

// ---------------- node_logits + delta_mu heads (16 i per block) ----------------
__global__ void __launch_bounds__(128)
heads_kernel(const float* __restrict__ Wn1, const float* __restrict__ bn1,
             const float* __restrict__ Wn2, const float* __restrict__ bn2,
             const float* __restrict__ Wd1, const float* __restrict__ bd1,
             const float* __restrict__ Wd2, const float* __restrict__ bd2,
             float* __restrict__ out) {
    __shared__ float hs[16][HID];
    __shared__ float redA[4][16], redB[4][16];
    int i0 = blockIdx.x * 16;
    int tid = threadIdx.x;
    int c = tid & 63, g = tid >> 6;

    for (int t = tid; t < 16 * HID; t += 128)
        hs[t >> 7][t & 127] = g_h[i0 * HID + t];
    __syncthreads();

    const float* W1 = g ? Wd1 : Wn1;
    float bb = g ? bd1[c] : bn1[c];
    float acc[16];
#pragma unroll
    for (int r = 0; r < 16; r++) acc[r] = bb;
    for (int k = 0; k < HID; k++) {
        float w = W1[k * 64 + c];
#pragma unroll
        for (int r = 0; r < 16; r++)
            acc[r] = fmaf(hs[r][k], w, acc[r]);
    }

    float w2a = g ? Wd2[c * 2 + 0] : Wn2[c];
    float w2b = g ? Wd2[c * 2 + 1] : 0.f;
    int warp = tid >> 5, lane = tid & 31;
#pragma unroll
    for (int r = 0; r < 16; r++) {
        float ar = fmaxf(acc[r], 0.f);
        float ya = ar * w2a, yb = ar * w2b;
#pragma unroll
        for (int o = 16; o; o >>= 1) {
            ya += __shfl_xor_sync(0xffffffffu, ya, o);
            yb += __shfl_xor_sync(0xffffffffu, yb, o);
        }
        if (lane == 0) { redA[warp][r] = ya; redB[warp][r] = yb; }
    }
    __syncthreads();

    if (tid < 16) {
        out[i0 + tid] = redA[0][tid] + redA[1][tid] + bn2[0];
    } else if (tid < 32) {
        int r = tid - 16;
        out[NN + 2 * (i0 + r) + 0] = redA[2][r] + redA[3][r] + bd2[0];
        out[NN + 2 * (i0 + r) + 1] = redB[2][r] + redB[3][r] + bd2[1];
    }
}

// ---------------- pooled value head ----------------
__global__ void pool_kernel() { // grid 8, block 128
    int b = blockIdx.x, c = threadIdx.x;
    float s = 0.f;
    for (int r = 0; r < 128; r++)
        s += g_h[(size_t)(b * 128 + r) * HID + c];
    g_pool[b * HID + c] = s;
}

__global__ void value_kernel(const float* __restrict__ Wv1, const float* __restrict__ bv1,
                             const float* __restrict__ Wv2, const float* __restrict__ bv2,
                             float* __restrict__ out) { // 1 block, 128 threads
    int t = threadIdx.x;
    __shared__ float ps[HID];
    float s = 0.f;
#pragma unroll
    for (int b = 0; b < 8; b++) s += g_pool[b * HID + t];
    ps[t] = s * (1.f / NN);
    __syncthreads();

    float p = 0.f;
    if (t < 64) {
        float a = bv1[t];
        for (int k = 0; k < HID; k++) a = fmaf(ps[k], Wv1[k * 64 + t], a);
        a = fmaxf(a, 0.f);
        p = a * Wv2[t];
    }
#pragma unroll
    for (int o = 16; o; o >>= 1) p += __shfl_xor_sync(0xffffffffu, p, o);
    __shared__ float red[4];
    if ((t & 31) == 0) red[t >> 5] = p;
    __syncthreads();
    if (t == 0) out[NN + 2 * NN] = red[0] + red[1] + red[2] + red[3] + bv2[0];
}

// ---------------- launch ----------------
extern "C" void kernel_launch(void* const* d_in, const int* in_sizes, int n_in,
                              void* d_out, int out_size) {
    const float* nf    = (const float*)d_in[0];
    const float* adj   = (const float*)d_in[1];
    const float* Wp    = (const float*)d_in[2];
    const float* bp    = (const float*)d_in[3];
    const float* Wl    = (const float*)d_in[4];
    const float* Wr    = (const float*)d_in[5];
    const float* Wv    = (const float*)d_in[6];
    const float* att   = (const float*)d_in[7];
    const float* gamma = (const float*)d_in[8];
    const float* beta  = (const float*)d_in[9];
    const float* Wn1   = (const float*)d_in[10];
    const float* bn1   = (const float*)d_in[11];
    const float* Wn2   = (const float*)d_in[12];
    const float* bn2   = (const float*)d_in[13];
    const float* Wd1   = (const float*)d_in[14];
    const float* bd1   = (const float*)d_in[15];
    const float* Wd2   = (const float*)d_in[16];
    const float* bd2   = (const float*)d_in[17];
    const float* Wv1   = (const float*)d_in[18];
    const float* bv1   = (const float*)d_in[19];
    const float* Wv2   = (const float*)d_in[20];
    const float* bv2   = (const float*)d_in[21];
    float* out = (float*)d_out;

    adjbits_kernel<<<128, 256>>>(adj);
    proj_kernel<<<NN, HID>>>(nf, Wp, bp);

    for (int l = 0; l < LAYERS; l++) {
        gemm3_kernel<<<dim3(32, 3), 128>>>(Wl + l * HID * HID,
                                           Wr + l * HID * HID,
                                           Wv + l * HID * HID);
        attn_kernel<<<NN / TI, 256>>>(att + l * HD, gamma + l * HID, beta + l * HID);
    }

    heads_kernel<<<64, 128>>>(Wn1, bn1, Wn2, bn2, Wd1, bd1, Wd2, bd2, out);
    pool_kernel<<<8, 128>>>();
    value_kernel<<<1, 128>>>(Wv1, bv1, Wv2, bv2, out);
}

// round 4
// speedup vs baseline: 4.1601x; 1.3236x over previous
#include <cuda_runtime.h>
#include <math_constants.h>

#define NN      1024
#define HID     128
#define HEADS   4
#define HD      32
#define LAYERS  3
#define TI      4          // i-rows per block in attention
#define NSEG    4          // j-segments (warp = head x seg)
#define SEGJ    (NN/NSEG)  // 256
#define ADJW    (NN/32)    // 32 words per adjacency row

// ---------------- scratch (no allocs allowed) ----------------
__device__ __align__(128) float    g_h[NN * HID];
__device__ __align__(128) float    g_wlh[NN * HID];
__device__ __align__(128) float    g_wrhT[HID * NN];   // [h*HD+d][j]
__device__ __align__(128) float    g_v[NN * HID];
__device__ __align__(128) unsigned g_adjbits[NN * ADJW];
__device__ __align__(128) float    g_pool[8 * HID];

// ---------------- adjacency -> bitmask ----------------
__global__ void adjbits_kernel(const float* __restrict__ adj) {
    int i    = blockIdx.x * 8 + (threadIdx.x >> 5);
    int lane = threadIdx.x & 31;
    for (int w = 0; w < ADJW; w++) {
        float v = adj[(size_t)i * NN + w * 32 + lane];
        unsigned b = __ballot_sync(0xffffffffu, v > 0.5f);
        if (lane == 0) g_adjbits[i * ADJW + w] = b;
    }
}

// ---------------- input projection: h = relu(nf @ Wp + bp) ----------------
__global__ void proj_kernel(const float* __restrict__ nf,
                            const float* __restrict__ Wp,
                            const float* __restrict__ bp) {
    int i = blockIdx.x;
    int c = threadIdx.x;
    float a = bp[c]
            + nf[i * 3 + 0] * Wp[0 * HID + c]
            + nf[i * 3 + 1] * Wp[1 * HID + c]
            + nf[i * 3 + 2] * Wp[2 * HID + c];
    g_h[i * HID + c] = fmaxf(a, 0.f);
}

// ---------------- 3-way projection GEMM ----------------
// grid (64, 3), block 128, 16 rows per block. y=0 -> wlh, y=1 -> wrhT, y=2 -> v.
__global__ void __launch_bounds__(128)
gemm3_kernel(const float* __restrict__ Wl,
             const float* __restrict__ Wr,
             const float* __restrict__ Wv) {
    __shared__ float hs[16 * 133];
    const float* W;
    float* O = nullptr;
    int mode = blockIdx.y;
    if (mode == 0)      { W = Wl; O = g_wlh; }
    else if (mode == 1) { W = Wr; }
    else                { W = Wv; O = g_v; }

    int r0 = blockIdx.x * 16;
    int c  = threadIdx.x;

    for (int t = c; t < 16 * HID; t += 128)
        hs[(t >> 7) * 133 + (t & 127)] = g_h[r0 * HID + t];
    __syncthreads();

    float acc[16];
#pragma unroll
    for (int r = 0; r < 16; r++) acc[r] = 0.f;

    for (int k = 0; k < HID; k++) {
        float w = W[k * HID + c];
#pragma unroll
        for (int r = 0; r < 16; r++)
            acc[r] = fmaf(hs[r * 133 + k], w, acc[r]);
    }

    if (mode != 1) {
#pragma unroll
        for (int r = 0; r < 16; r++)
            O[(r0 + r) * HID + c] = acc[r];
    } else {
        __syncthreads();
#pragma unroll
        for (int r = 0; r < 16; r++)
            hs[r * 133 + c] = acc[r];
        __syncthreads();
        int lane = c & 15, grp = c >> 4;   // 8 groups x 16 lanes
        for (int cc = grp; cc < HID; cc += 8)
            g_wrhT[cc * NN + r0 + lane] = hs[lane * 133 + cc];
    }
}

// ---------------- fused GATv2 attention + merge + LN + residual ----------------
// grid NN/TI = 256 blocks, 512 threads = 16 warps: warp = (head h = w&3, seg = w>>2).
// No online max (softmax shift-invariance; exponent is O(+-20), safe in fp32).
__global__ void __launch_bounds__(512, 2)
attn_kernel(const float* __restrict__ att,
            const float* __restrict__ gamma,
            const float* __restrict__ beta) {
    const int i0   = blockIdx.x * TI;
    const int tid  = threadIdx.x;
    const int warp = tid >> 5;
    const int lane = tid & 31;
    const int h    = warp & 3;
    const int seg  = warp >> 2;

    __shared__ __align__(16) float wl_s[TI][HID];
    __shared__ __align__(16) float att_s[HD];
    __shared__ __align__(16) float p_s[16][32][4];    // [warp][jj][ii]
    __shared__ float s_s[HEADS][NSEG][TI];
    __shared__ float acc_s[HEADS][NSEG][TI][HD];
    __shared__ __align__(16) float agg_s[TI][HID];

    for (int t = tid; t < TI * HID; t += 512)
        wl_s[t >> 7][t & 127] = g_wlh[i0 * HID + t];
    if (tid < HD) att_s[tid] = att[tid];
    __syncthreads();

    float s0 = 0.f, s1 = 0.f, s2 = 0.f, s3 = 0.f;
    float a0 = 0.f, a1 = 0.f, a2 = 0.f, a3 = 0.f;   // acc, lane = d

    const int jbase = seg * SEGJ;
#pragma unroll 1
    for (int c = 0; c < SEGJ / 32; c++) {
        const int j0 = jbase + c * 32;
        const int j  = j0 + lane;

        float b = 0.f, c0 = 0.f, c1 = 0.f, c2 = 0.f, c3 = 0.f;

        // ---- scores: two half-passes over d to cap live registers ----
#pragma unroll
        for (int half = 0; half < 2; half++) {
            float wr[16];
#pragma unroll
            for (int d = 0; d < 16; d++)
                wr[d] = g_wrhT[(h * HD + half * 16 + d) * NN + j];
#pragma unroll
            for (int q = 0; q < 4; q++) {
                float4 at = *(const float4*)&att_s[half * 16 + 4 * q];
                float w0 = wr[4*q+0], w1 = wr[4*q+1], w2 = wr[4*q+2], w3 = wr[4*q+3];
                b = fmaf(w0, at.x, b); b = fmaf(w1, at.y, b);
                b = fmaf(w2, at.z, b); b = fmaf(w3, at.w, b);
                const int off = h * HD + half * 16 + 4 * q;
                float4 l;
                l = *(const float4*)&wl_s[0][off];
                c0 = fmaf(fabsf(l.x + w0), at.x, c0); c0 = fmaf(fabsf(l.y + w1), at.y, c0);
                c0 = fmaf(fabsf(l.z + w2), at.z, c0); c0 = fmaf(fabsf(l.w + w3), at.w, c0);
                l = *(const float4*)&wl_s[1][off];
                c1 = fmaf(fabsf(l.x + w0), at.x, c1); c1 = fmaf(fabsf(l.y + w1), at.y, c1);
                c1 = fmaf(fabsf(l.z + w2), at.z, c1); c1 = fmaf(fabsf(l.w + w3), at.w, c1);
                l = *(const float4*)&wl_s[2][off];
                c2 = fmaf(fabsf(l.x + w0), at.x, c2); c2 = fmaf(fabsf(l.y + w1), at.y, c2);
                c2 = fmaf(fabsf(l.z + w2), at.z, c2); c2 = fmaf(fabsf(l.w + w3), at.w, c2);
                l = *(const float4*)&wl_s[3][off];
                c3 = fmaf(fabsf(l.x + w0), at.x, c3); c3 = fmaf(fabsf(l.y + w1), at.y, c3);
                c3 = fmaf(fabsf(l.z + w2), at.z, c3); c3 = fmaf(fabsf(l.w + w3), at.w, c3);
            }
        }
        float b6 = 0.6f * b;

        const int widx = j0 >> 5;
        unsigned aw0 = g_adjbits[(i0 + 0) * ADJW + widx];
        unsigned aw1 = g_adjbits[(i0 + 1) * ADJW + widx];
        unsigned aw2 = g_adjbits[(i0 + 2) * ADJW + widx];
        unsigned aw3 = g_adjbits[(i0 + 3) * ADJW + widx];
        float p0 = ((aw0 >> lane) & 1u) ? __expf(fmaf(0.4f, c0, b6)) : 0.f;
        float p1 = ((aw1 >> lane) & 1u) ? __expf(fmaf(0.4f, c1, b6)) : 0.f;
        float p2 = ((aw2 >> lane) & 1u) ? __expf(fmaf(0.4f, c2, b6)) : 0.f;
        float p3 = ((aw3 >> lane) & 1u) ? __expf(fmaf(0.4f, c3, b6)) : 0.f;
        s0 += p0; s1 += p1; s2 += p2; s3 += p3;

        *(float4*)&p_s[warp][lane][0] = make_float4(p0, p1, p2, p3);
        __syncwarp();

        // ---- acc[d=lane] += p[jj] * v[j0+jj, h, lane], two half-passes ----
        const float* vb = g_v + (size_t)j0 * HID + h * HD + lane;
#pragma unroll
        for (int half = 0; half < 2; half++) {
            float vv[16];
#pragma unroll
            for (int jj = 0; jj < 16; jj++)
                vv[jj] = vb[(size_t)(half * 16 + jj) * HID];
#pragma unroll
            for (int jj = 0; jj < 16; jj++) {
                float4 pj = *(const float4*)&p_s[warp][half * 16 + jj][0];
                a0 = fmaf(pj.x, vv[jj], a0);
                a1 = fmaf(pj.y, vv[jj], a1);
                a2 = fmaf(pj.z, vv[jj], a2);
                a3 = fmaf(pj.w, vv[jj], a3);
            }
        }
        __syncwarp();
    }

    // ---- publish per-segment sums ----
    float sv[4] = {s0, s1, s2, s3};
    float av[4] = {a0, a1, a2, a3};
#pragma unroll
    for (int ii = 0; ii < TI; ii++) {
        float t = sv[ii];
#pragma unroll
        for (int o = 16; o; o >>= 1) t += __shfl_xor_sync(0xffffffffu, t, o);
        if (lane == 0) s_s[h][seg][ii] = t;
        acc_s[h][seg][ii][lane] = av[ii];
    }
    __syncthreads();

    // ---- merge 4 segments per (i, head): warp w handles ii=w>>2, hh=w&3 ----
    {
        int ii = warp >> 2, hh = warp & 3;
        float S = s_s[hh][0][ii] + s_s[hh][1][ii] + s_s[hh][2][ii] + s_s[hh][3][ii];
        float A = acc_s[hh][0][ii][lane] + acc_s[hh][1][ii][lane]
                + acc_s[hh][2][ii][lane] + acc_s[hh][3][ii][lane];
        agg_s[ii][hh * HD + lane] = A / S;
    }
    __syncthreads();

    // ---- LN + relu + residual (warp = row) ----
    if (warp < TI) {
        const int ii = warp;
        float4 x = *(const float4*)&agg_s[ii][lane * 4];
        float m1 = x.x + x.y + x.z + x.w;
        float m2 = x.x*x.x + x.y*x.y + x.z*x.z + x.w*x.w;
#pragma unroll
        for (int o = 16; o; o >>= 1) {
            m1 += __shfl_xor_sync(0xffffffffu, m1, o);
            m2 += __shfl_xor_sync(0xffffffffu, m2, o);
        }
        float mu  = m1 * (1.f / HID);
        float var = m2 * (1.f / HID) - mu * mu;
        float rs  = rsqrtf(var + 1e-5f);
        float4 gm = *(const float4*)&gamma[lane * 4];
        float4 bt = *(const float4*)&beta[lane * 4];
        float4 hv = *(float4*)&g_h[(i0 + ii) * HID + lane * 4];
        hv.x += fmaxf((x.x - mu) * rs * gm.x + bt.x, 0.f);
        hv.y += fmaxf((x.y - mu) * rs * gm.y + bt.y, 0.f);
        hv.z += fmaxf((x.z - mu) * rs * gm.z + bt.z, 0.f);
        hv.w += fmaxf((x.w - mu) * rs * gm.w + bt.w, 0.f);
        *(float4*)&g_h[(i0 + ii) * HID + lane * 4] = hv;
    }
}

// ---------------- node_logits + delta_mu heads (16 i per block) ----------------
__global__ void __launch_bounds__(128)
heads_kernel(const float* __restrict__ Wn1, const float* __restrict__ bn1,
             const float* __restrict__ Wn2, const float* __restrict__ bn2,
             const float* __restrict__ Wd1, const float* __restrict__ bd1,
             const float* __restrict__ Wd2, const float* __restrict__ bd2,
             float* __restrict__ out) {
    __shared__ float hs[16][HID];
    __shared__ float redA[4][16], redB[4][16];
    int i0 = blockIdx.x * 16;
    int tid = threadIdx.x;
    int c = tid & 63, g = tid >> 6;

    for (int t = tid; t < 16 * HID; t += 128)
        hs[t >> 7][t & 127] = g_h[i0 * HID + t];
    __syncthreads();

    const float* W1 = g ? Wd1 : Wn1;
    float bb = g ? bd1[c] : bn1[c];
    float acc[16];
#pragma unroll
    for (int r = 0; r < 16; r++) acc[r] = bb;
    for (int k = 0; k < HID; k++) {
        float w = W1[k * 64 + c];
#pragma unroll
        for (int r = 0; r < 16; r++)
            acc[r] = fmaf(hs[r][k], w, acc[r]);
    }

    float w2a = g ? Wd2[c * 2 + 0] : Wn2[c];
    float w2b = g ? Wd2[c * 2 + 1] : 0.f;
    int warp = tid >> 5, lane = tid & 31;
#pragma unroll
    for (int r = 0; r < 16; r++) {
        float ar = fmaxf(acc[r], 0.f);
        float ya = ar * w2a, yb = ar * w2b;
#pragma unroll
        for (int o = 16; o; o >>= 1) {
            ya += __shfl_xor_sync(0xffffffffu, ya, o);
            yb += __shfl_xor_sync(0xffffffffu, yb, o);
        }
        if (lane == 0) { redA[warp][r] = ya; redB[warp][r] = yb; }
    }
    __syncthreads();

    if (tid < 16) {
        out[i0 + tid] = redA[0][tid] + redA[1][tid] + bn2[0];
    } else if (tid < 32) {
        int r = tid - 16;
        out[NN + 2 * (i0 + r) + 0] = redA[2][r] + redA[3][r] + bd2[0];
        out[NN + 2 * (i0 + r) + 1] = redB[2][r] + redB[3][r] + bd2[1];
    }
}

// ---------------- pooled value head ----------------
__global__ void pool_kernel() { // grid 8, block 128
    int b = blockIdx.x, c = threadIdx.x;
    float s = 0.f;
    for (int r = 0; r < 128; r++)
        s += g_h[(size_t)(b * 128 + r) * HID + c];
    g_pool[b * HID + c] = s;
}

__global__ void value_kernel(const float* __restrict__ Wv1, const float* __restrict__ bv1,
                             const float* __restrict__ Wv2, const float* __restrict__ bv2,
                             float* __restrict__ out) { // 1 block, 128 threads
    int t = threadIdx.x;
    __shared__ float ps[HID];
    float s = 0.f;
#pragma unroll
    for (int b = 0; b < 8; b++) s += g_pool[b * HID + t];
    ps[t] = s * (1.f / NN);
    __syncthreads();

    float p = 0.f;
    if (t < 64) {
        float a = bv1[t];
        for (int k = 0; k < HID; k++) a = fmaf(ps[k], Wv1[k * 64 + t], a);
        a = fmaxf(a, 0.f);
        p = a * Wv2[t];
    }
#pragma unroll
    for (int o = 16; o; o >>= 1) p += __shfl_xor_sync(0xffffffffu, p, o);
    __shared__ float red[4];
    if ((t & 31) == 0) red[t >> 5] = p;
    __syncthreads();
    if (t == 0) out[NN + 2 * NN] = red[0] + red[1] + red[2] + red[3] + bv2[0];
}

// ---------------- launch ----------------
extern "C" void kernel_launch(void* const* d_in, const int* in_sizes, int n_in,
                              void* d_out, int out_size) {
    const float* nf    = (const float*)d_in[0];
    const float* adj   = (const float*)d_in[1];
    const float* Wp    = (const float*)d_in[2];
    const float* bp    = (const float*)d_in[3];
    const float* Wl    = (const float*)d_in[4];
    const float* Wr    = (const float*)d_in[5];
    const float* Wv    = (const float*)d_in[6];
    const float* att   = (const float*)d_in[7];
    const float* gamma = (const float*)d_in[8];
    const float* beta  = (const float*)d_in[9];
    const float* Wn1   = (const float*)d_in[10];
    const float* bn1   = (const float*)d_in[11];
    const float* Wn2   = (const float*)d_in[12];
    const float* bn2   = (const float*)d_in[13];
    const float* Wd1   = (const float*)d_in[14];
    const float* bd1   = (const float*)d_in[15];
    const float* Wd2   = (const float*)d_in[16];
    const float* bd2   = (const float*)d_in[17];
    const float* Wv1   = (const float*)d_in[18];
    const float* bv1   = (const float*)d_in[19];
    const float* Wv2   = (const float*)d_in[20];
    const float* bv2   = (const float*)d_in[21];
    float* out = (float*)d_out;

    adjbits_kernel<<<128, 256>>>(adj);
    proj_kernel<<<NN, HID>>>(nf, Wp, bp);

    for (int l = 0; l < LAYERS; l++) {
        gemm3_kernel<<<dim3(64, 3), 128>>>(Wl + l * HID * HID,
                                           Wr + l * HID * HID,
                                           Wv + l * HID * HID);
        attn_kernel<<<NN / TI, 512>>>(att + l * HD, gamma + l * HID, beta + l * HID);
    }

    heads_kernel<<<64, 128>>>(Wn1, bn1, Wn2, bn2, Wd1, bd1, Wd2, bd2, out);
    pool_kernel<<<8, 128>>>();
    value_kernel<<<1, 128>>>(Wv1, bv1, Wv2, bv2, out);
}

// round 5
// speedup vs baseline: 4.4041x; 1.0587x over previous
#include <cuda_runtime.h>
#include <math_constants.h>

#define NN      1024
#define HID     128
#define HEADS   4
#define HD      32
#define LAYERS  3
#define TI      4          // i-rows per block in attention
#define NSEG    4          // j-segments (warp = head x seg)
#define SEGJ    (NN/NSEG)  // 256
#define ADJW    (NN/32)    // 32 words per adjacency row

// ---------------- scratch (no allocs allowed) ----------------
__device__ __align__(128) float    g_h[NN * HID];
__device__ __align__(128) float    g_wlh[NN * HID];
__device__ __align__(128) float    g_wrhT[HID * NN];   // [h*HD+d][j]
__device__ __align__(128) float    g_v[NN * HID];
__device__ __align__(128) float    g_eb[HEADS * NN];   // exp(0.6 * sum_d wrh*att)
__device__ __align__(128) unsigned g_adjbits[ADJW * NN]; // [word][i] transposed
__device__ __align__(128) float    g_pool[8 * HID];

// ---------------- adjacency -> bitmask (transposed [w][i]) ----------------
__global__ void adjbits_kernel(const float* __restrict__ adj) {
    int i    = blockIdx.x * 8 + (threadIdx.x >> 5);
    int lane = threadIdx.x & 31;
    for (int w = 0; w < ADJW; w++) {
        float v = adj[(size_t)i * NN + w * 32 + lane];
        unsigned b = __ballot_sync(0xffffffffu, v > 0.5f);
        if (lane == 0) g_adjbits[w * NN + i] = b;
    }
}

// ---------------- input projection: h = relu(nf @ Wp + bp) ----------------
__global__ void proj_kernel(const float* __restrict__ nf,
                            const float* __restrict__ Wp,
                            const float* __restrict__ bp) {
    int i = blockIdx.x;
    int c = threadIdx.x;
    float a = bp[c]
            + nf[i * 3 + 0] * Wp[0 * HID + c]
            + nf[i * 3 + 1] * Wp[1 * HID + c]
            + nf[i * 3 + 2] * Wp[2 * HID + c];
    g_h[i * HID + c] = fmaxf(a, 0.f);
}

// ---------------- 3-way projection GEMM ----------------
// grid (64, 3), block 128, 16 rows per block. y=0 -> wlh, y=1 -> wrhT+eb, y=2 -> v.
__global__ void __launch_bounds__(128)
gemm3_kernel(const float* __restrict__ Wl,
             const float* __restrict__ Wr,
             const float* __restrict__ Wv,
             const float* __restrict__ att) {
    __shared__ float hs[16 * 132];   // stride 132: 16B-aligned float4, conflict-free
    int mode = blockIdx.y;
    const float* W = (mode == 0) ? Wl : (mode == 1 ? Wr : Wv);

    int r0 = blockIdx.x * 16;
    int c  = threadIdx.x;

    for (int t = c; t < 16 * HID; t += 128)
        hs[(t >> 7) * 132 + (t & 127)] = g_h[r0 * HID + t];
    __syncthreads();

    float acc[16];
#pragma unroll
    for (int r = 0; r < 16; r++) acc[r] = 0.f;

#pragma unroll 4
    for (int k4 = 0; k4 < HID / 4; k4++) {
        float w0 = W[(4 * k4 + 0) * HID + c];
        float w1 = W[(4 * k4 + 1) * HID + c];
        float w2 = W[(4 * k4 + 2) * HID + c];
        float w3 = W[(4 * k4 + 3) * HID + c];
#pragma unroll
        for (int r = 0; r < 16; r++) {
            float4 hv = *(const float4*)&hs[r * 132 + 4 * k4];
            acc[r] = fmaf(hv.x, w0, acc[r]);
            acc[r] = fmaf(hv.y, w1, acc[r]);
            acc[r] = fmaf(hv.z, w2, acc[r]);
            acc[r] = fmaf(hv.w, w3, acc[r]);
        }
    }

    if (mode == 0) {
#pragma unroll
        for (int r = 0; r < 16; r++)
            g_wlh[(r0 + r) * HID + c] = acc[r];
    } else if (mode == 2) {
#pragma unroll
        for (int r = 0; r < 16; r++)
            g_v[(r0 + r) * HID + c] = acc[r];
    } else {
        // eb: per head-warp reduce acc[r]*att over d
        int lane = c & 31, hd = c >> 5;
        float atv = att[lane];
#pragma unroll
        for (int r = 0; r < 16; r++) {
            float bv = acc[r] * atv;
#pragma unroll
            for (int o = 16; o; o >>= 1) bv += __shfl_xor_sync(0xffffffffu, bv, o);
            if (lane == 0) g_eb[hd * NN + r0 + r] = __expf(0.6f * bv);
        }
        __syncthreads();
#pragma unroll
        for (int r = 0; r < 16; r++)
            hs[r * 132 + c] = acc[r];
        __syncthreads();
        int l16 = c & 15, grp = c >> 4;   // 8 groups x 16 lanes
        for (int cc = grp; cc < HID; cc += 8)
            g_wrhT[cc * NN + r0 + l16] = hs[l16 * 132 + cc];
    }
}

// ---------------- fused GATv2 attention + merge + LN + residual ----------------
// grid NN/TI = 256 blocks, 512 threads = 16 warps: warp = (head h = w&3, seg = w>>2).
// No online max (softmax shift-invariance; exponent O(+-20), safe in fp32).
// p = eb_j * exp(0.4 * sum |wl+wr| att)  with 0.4 prefolded into att_s.
__global__ void __launch_bounds__(512, 2)
attn_kernel(const float* __restrict__ att,
            const float* __restrict__ gamma,
            const float* __restrict__ beta) {
    const int i0   = blockIdx.x * TI;
    const int tid  = threadIdx.x;
    const int warp = tid >> 5;
    const int lane = tid & 31;
    const int h    = warp & 3;
    const int seg  = warp >> 2;

    __shared__ __align__(16) float wl_s[TI][HID];
    __shared__ __align__(16) float att_s[HD];
    __shared__ __align__(16) float p_s[16][32][4];    // [warp][jj][ii]
    __shared__ float s_s[HEADS][NSEG][TI];
    __shared__ float acc_s[HEADS][NSEG][TI][HD];
    __shared__ __align__(16) float agg_s[TI][HID];

    for (int t = tid; t < TI * HID; t += 512)
        wl_s[t >> 7][t & 127] = g_wlh[i0 * HID + t];
    if (tid < HD) att_s[tid] = 0.4f * att[tid];
    __syncthreads();

    float s0 = 0.f, s1 = 0.f, s2 = 0.f, s3 = 0.f;
    float a0 = 0.f, a1 = 0.f, a2 = 0.f, a3 = 0.f;   // acc, lane = d

    const int jbase = seg * SEGJ;
#pragma unroll 1
    for (int c = 0; c < SEGJ / 32; c++) {
        const int j0 = jbase + c * 32;
        const int j  = j0 + lane;

        float ebv = g_eb[h * NN + j];
        uint4 aw  = *(const uint4*)&g_adjbits[(j0 >> 5) * NN + i0];

        float c0 = 0.f, c1 = 0.f, c2 = 0.f, c3 = 0.f;

        // ---- scores: two half-passes over d to cap live registers ----
#pragma unroll
        for (int half = 0; half < 2; half++) {
            float wr[16];
#pragma unroll
            for (int d = 0; d < 16; d++)
                wr[d] = g_wrhT[(h * HD + half * 16 + d) * NN + j];
#pragma unroll
            for (int q = 0; q < 4; q++) {
                float4 at = *(const float4*)&att_s[half * 16 + 4 * q];
                float w0 = wr[4*q+0], w1 = wr[4*q+1], w2 = wr[4*q+2], w3 = wr[4*q+3];
                const int off = h * HD + half * 16 + 4 * q;
                float4 l;
                l = *(const float4*)&wl_s[0][off];
                c0 = fmaf(fabsf(l.x + w0), at.x, c0); c0 = fmaf(fabsf(l.y + w1), at.y, c0);
                c0 = fmaf(fabsf(l.z + w2), at.z, c0); c0 = fmaf(fabsf(l.w + w3), at.w, c0);
                l = *(const float4*)&wl_s[1][off];
                c1 = fmaf(fabsf(l.x + w0), at.x, c1); c1 = fmaf(fabsf(l.y + w1), at.y, c1);
                c1 = fmaf(fabsf(l.z + w2), at.z, c1); c1 = fmaf(fabsf(l.w + w3), at.w, c1);
                l = *(const float4*)&wl_s[2][off];
                c2 = fmaf(fabsf(l.x + w0), at.x, c2); c2 = fmaf(fabsf(l.y + w1), at.y, c2);
                c2 = fmaf(fabsf(l.z + w2), at.z, c2); c2 = fmaf(fabsf(l.w + w3), at.w, c2);
                l = *(const float4*)&wl_s[3][off];
                c3 = fmaf(fabsf(l.x + w0), at.x, c3); c3 = fmaf(fabsf(l.y + w1), at.y, c3);
                c3 = fmaf(fabsf(l.z + w2), at.z, c3); c3 = fmaf(fabsf(l.w + w3), at.w, c3);
            }
        }

        float p0 = ((aw.x >> lane) & 1u) ? ebv * __expf(c0) : 0.f;
        float p1 = ((aw.y >> lane) & 1u) ? ebv * __expf(c1) : 0.f;
        float p2 = ((aw.z >> lane) & 1u) ? ebv * __expf(c2) : 0.f;
        float p3 = ((aw.w >> lane) & 1u) ? ebv * __expf(c3) : 0.f;
        s0 += p0; s1 += p1; s2 += p2; s3 += p3;

        *(float4*)&p_s[warp][lane][0] = make_float4(p0, p1, p2, p3);
        __syncwarp();

        // ---- acc[d=lane] += p[jj] * v[j0+jj, h, lane], two half-passes ----
        const float* vb = g_v + (size_t)j0 * HID + h * HD + lane;
#pragma unroll
        for (int half = 0; half < 2; half++) {
            float vv[16];
#pragma unroll
            for (int jj = 0; jj < 16; jj++)
                vv[jj] = vb[(size_t)(half * 16 + jj) * HID];
#pragma unroll
            for (int jj = 0; jj < 16; jj++) {
                float4 pj = *(const float4*)&p_s[warp][half * 16 + jj][0];
                a0 = fmaf(pj.x, vv[jj], a0);
                a1 = fmaf(pj.y, vv[jj], a1);
                a2 = fmaf(pj.z, vv[jj], a2);
                a3 = fmaf(pj.w, vv[jj], a3);
            }
        }
        __syncwarp();
    }

    // ---- publish per-segment sums ----
    float sv[4] = {s0, s1, s2, s3};
    float av[4] = {a0, a1, a2, a3};
#pragma unroll
    for (int ii = 0; ii < TI; ii++) {
        float t = sv[ii];
#pragma unroll
        for (int o = 16; o; o >>= 1) t += __shfl_xor_sync(0xffffffffu, t, o);
        if (lane == 0) s_s[h][seg][ii] = t;
        acc_s[h][seg][ii][lane] = av[ii];
    }
    __syncthreads();

    // ---- merge 4 segments per (i, head): warp w handles ii=w>>2, hh=w&3 ----
    {
        int ii = warp >> 2, hh = warp & 3;
        float S = s_s[hh][0][ii] + s_s[hh][1][ii] + s_s[hh][2][ii] + s_s[hh][3][ii];
        float A = acc_s[hh][0][ii][lane] + acc_s[hh][1][ii][lane]
                + acc_s[hh][2][ii][lane] + acc_s[hh][3][ii][lane];
        agg_s[ii][hh * HD + lane] = A / S;
    }
    __syncthreads();

    // ---- LN + relu + residual (warp = row) ----
    if (warp < TI) {
        const int ii = warp;
        float4 x = *(const float4*)&agg_s[ii][lane * 4];
        float m1 = x.x + x.y + x.z + x.w;
        float m2 = x.x*x.x + x.y*x.y + x.z*x.z + x.w*x.w;
#pragma unroll
        for (int o = 16; o; o >>= 1) {
            m1 += __shfl_xor_sync(0xffffffffu, m1, o);
            m2 += __shfl_xor_sync(0xffffffffu, m2, o);
        }
        float mu  = m1 * (1.f / HID);
        float var = m2 * (1.f / HID) - mu * mu;
        float rs  = rsqrtf(var + 1e-5f);
        float4 gm = *(const float4*)&gamma[lane * 4];
        float4 bt = *(const float4*)&beta[lane * 4];
        float4 hv = *(float4*)&g_h[(i0 + ii) * HID + lane * 4];
        hv.x += fmaxf((x.x - mu) * rs * gm.x + bt.x, 0.f);
        hv.y += fmaxf((x.y - mu) * rs * gm.y + bt.y, 0.f);
        hv.z += fmaxf((x.z - mu) * rs * gm.z + bt.z, 0.f);
        hv.w += fmaxf((x.w - mu) * rs * gm.w + bt.w, 0.f);
        *(float4*)&g_h[(i0 + ii) * HID + lane * 4] = hv;
    }
}

// ---------------- node_logits + delta_mu heads (16 i per block) ----------------
__global__ void __launch_bounds__(128)
heads_kernel(const float* __restrict__ Wn1, const float* __restrict__ bn1,
             const float* __restrict__ Wn2, const float* __restrict__ bn2,
             const float* __restrict__ Wd1, const float* __restrict__ bd1,
             const float* __restrict__ Wd2, const float* __restrict__ bd2,
             float* __restrict__ out) {
    __shared__ __align__(16) float hs[16][HID];
    __shared__ float redA[4][16], redB[4][16];
    int i0 = blockIdx.x * 16;
    int tid = threadIdx.x;
    int c = tid & 63, g = tid >> 6;

    for (int t = tid; t < 16 * HID; t += 128)
        hs[t >> 7][t & 127] = g_h[i0 * HID + t];
    __syncthreads();

    const float* W1 = g ? Wd1 : Wn1;
    float bb = g ? bd1[c] : bn1[c];
    float acc[16];
#pragma unroll
    for (int r = 0; r < 16; r++) acc[r] = bb;
#pragma unroll 4
    for (int k4 = 0; k4 < HID / 4; k4++) {
        float w0 = W1[(4 * k4 + 0) * 64 + c];
        float w1 = W1[(4 * k4 + 1) * 64 + c];
        float w2 = W1[(4 * k4 + 2) * 64 + c];
        float w3 = W1[(4 * k4 + 3) * 64 + c];
#pragma unroll
        for (int r = 0; r < 16; r++) {
            float4 hv = *(const float4*)&hs[r][4 * k4];
            acc[r] = fmaf(hv.x, w0, acc[r]);
            acc[r] = fmaf(hv.y, w1, acc[r]);
            acc[r] = fmaf(hv.z, w2, acc[r]);
            acc[r] = fmaf(hv.w, w3, acc[r]);
        }
    }

    float w2a = g ? Wd2[c * 2 + 0] : Wn2[c];
    float w2b = g ? Wd2[c * 2 + 1] : 0.f;
    int warp = tid >> 5, lane = tid & 31;
#pragma unroll
    for (int r = 0; r < 16; r++) {
        float ar = fmaxf(acc[r], 0.f);
        float ya = ar * w2a, yb = ar * w2b;
#pragma unroll
        for (int o = 16; o; o >>= 1) {
            ya += __shfl_xor_sync(0xffffffffu, ya, o);
            yb += __shfl_xor_sync(0xffffffffu, yb, o);
        }
        if (lane == 0) { redA[warp][r] = ya; redB[warp][r] = yb; }
    }
    __syncthreads();

    if (tid < 16) {
        out[i0 + tid] = redA[0][tid] + redA[1][tid] + bn2[0];
    } else if (tid < 32) {
        int r = tid - 16;
        out[NN + 2 * (i0 + r) + 0] = redA[2][r] + redA[3][r] + bd2[0];
        out[NN + 2 * (i0 + r) + 1] = redB[2][r] + redB[3][r] + bd2[1];
    }
}

// ---------------- pooled value head ----------------
__global__ void pool_kernel() { // grid 8, block 128
    int b = blockIdx.x, c = threadIdx.x;
    float s = 0.f;
    for (int r = 0; r < 128; r++)
        s += g_h[(size_t)(b * 128 + r) * HID + c];
    g_pool[b * HID + c] = s;
}

__global__ void value_kernel(const float* __restrict__ Wv1, const float* __restrict__ bv1,
                             const float* __restrict__ Wv2, const float* __restrict__ bv2,
                             float* __restrict__ out) { // 1 block, 128 threads
    int t = threadIdx.x;
    __shared__ float ps[HID];
    float s = 0.f;
#pragma unroll
    for (int b = 0; b < 8; b++) s += g_pool[b * HID + t];
    ps[t] = s * (1.f / NN);
    __syncthreads();

    float p = 0.f;
    if (t < 64) {
        float a = bv1[t];
        for (int k = 0; k < HID; k++) a = fmaf(ps[k], Wv1[k * 64 + t], a);
        a = fmaxf(a, 0.f);
        p = a * Wv2[t];
    }
#pragma unroll
    for (int o = 16; o; o >>= 1) p += __shfl_xor_sync(0xffffffffu, p, o);
    __shared__ float red[4];
    if ((t & 31) == 0) red[t >> 5] = p;
    __syncthreads();
    if (t == 0) out[NN + 2 * NN] = red[0] + red[1] + red[2] + red[3] + bv2[0];
}

// ---------------- launch ----------------
extern "C" void kernel_launch(void* const* d_in, const int* in_sizes, int n_in,
                              void* d_out, int out_size) {
    const float* nf    = (const float*)d_in[0];
    const float* adj   = (const float*)d_in[1];
    const float* Wp    = (const float*)d_in[2];
    const float* bp    = (const float*)d_in[3];
    const float* Wl    = (const float*)d_in[4];
    const float* Wr    = (const float*)d_in[5];
    const float* Wv    = (const float*)d_in[6];
    const float* att   = (const float*)d_in[7];
    const float* gamma = (const float*)d_in[8];
    const float* beta  = (const float*)d_in[9];
    const float* Wn1   = (const float*)d_in[10];
    const float* bn1   = (const float*)d_in[11];
    const float* Wn2   = (const float*)d_in[12];
    const float* bn2   = (const float*)d_in[13];
    const float* Wd1   = (const float*)d_in[14];
    const float* bd1   = (const float*)d_in[15];
    const float* Wd2   = (const float*)d_in[16];
    const float* bd2   = (const float*)d_in[17];
    const float* Wv1   = (const float*)d_in[18];
    const float* bv1   = (const float*)d_in[19];
    const float* Wv2   = (const float*)d_in[20];
    const float* bv2   = (const float*)d_in[21];
    float* out = (float*)d_out;

    adjbits_kernel<<<128, 256>>>(adj);
    proj_kernel<<<NN, HID>>>(nf, Wp, bp);

    for (int l = 0; l < LAYERS; l++) {
        gemm3_kernel<<<dim3(64, 3), 128>>>(Wl + l * HID * HID,
                                           Wr + l * HID * HID,
                                           Wv + l * HID * HID,
                                           att + l * HD);
        attn_kernel<<<NN / TI, 512>>>(att + l * HD, gamma + l * HID, beta + l * HID);
    }

    heads_kernel<<<64, 128>>>(Wn1, bn1, Wn2, bn2, Wd1, bd1, Wd2, bd2, out);
    pool_kernel<<<8, 128>>>();
    value_kernel<<<1, 128>>>(Wv1, bv1, Wv2, bv2, out);
}